// round 1
// baseline (speedup 1.0000x reference)
#include <cuda_runtime.h>
#include <cstdint>

#define Bb 4
#define Mm 256
#define Tt 64
#define BT 256      // B*T
#define KD 512      // 2M == D_MOT == D_ABS
#define DOUT 768

// Scratch (no allocation allowed -> __device__ globals)
__device__ float d_V [Mm*BT];              // V [j][bt] = vis_eff
__device__ float d_VX[Mm*BT];              // x_clean * vis_eff
__device__ float d_VY[Mm*BT];              // y_clean * vis_eff
__device__ float d_S [3*BT*KD];            // S rows: r*256+bt, 512 cols
__device__ float d_cvec[DOUT];             // fc1_b@W2_top + fc_out_b
__device__ float d_AB[(3*BT + Mm)*DOUT];   // rows 0..767: A0/A1/AU ; rows 768..1023: base[m]

__device__ __forceinline__ bool is_nan_bits(float x) {
    return (__float_as_uint(x) & 0x7fffffffu) > 0x7f800000u;
}

// ---------------------------------------------------------------------------
// prep: build V/VX/VY in (j, bt) layout.  grid=(256 j), block=256 (b*64+t)
// ---------------------------------------------------------------------------
__global__ void prep_kernel(const float* __restrict__ coords,
                            const float* __restrict__ vis) {
    int j = blockIdx.x;
    int t = threadIdx.x;           // == bt = b*64 + tt
    int b = t >> 6, tt = t & 63;
    int idx = (b*Mm + j)*Tt + tt;
    float2 xy = ((const float2*)coords)[idx];
    float v = vis[idx];
    float x = xy.x, y = xy.y;
    if (is_nan_bits(x)) { v = 0.f; x = 0.f; }
    if (is_nan_bits(y)) { y = 0.f; }
    int o = j*BT + t;
    d_V [o] = v;
    d_VX[o] = x * v;
    d_VY[o] = y * v;
}

// ---------------------------------------------------------------------------
// stage1: S0 = V@We, S1 = V@Wo, SU = VX@We + VY@Wo   (contraction over j=256)
// grid=(8 bt-tiles of 32, 16 k-tiles of 32), block=256, 2x2 microtile x3 outs
// ---------------------------------------------------------------------------
__global__ void stage1_kernel(const float* __restrict__ fc1w) {
    __shared__ float Vt [16][32], VXt[16][32], VYt[16][32];
    __shared__ float W0t[16][32], W1t[16][32];
    int bt0 = blockIdx.x * 32;
    int k0  = blockIdx.y * 32;
    int t  = threadIdx.x;
    int tx = t & 15;       // k pair
    int ty = t >> 4;       // bt pair
    float s0[2][2] = {{0,0},{0,0}};
    float s1[2][2] = {{0,0},{0,0}};
    float su[2][2] = {{0,0},{0,0}};
    int lj = t >> 4;           // load row 0..15
    int lc = (t & 15) * 2;     // load col pair

    for (int jc = 0; jc < Mm; jc += 16) {
        float2 tv  = *(const float2*)&d_V [(jc+lj)*BT + bt0 + lc];
        float2 tvx = *(const float2*)&d_VX[(jc+lj)*BT + bt0 + lc];
        float2 tvy = *(const float2*)&d_VY[(jc+lj)*BT + bt0 + lc];
        Vt [lj][lc] = tv.x;  Vt [lj][lc+1] = tv.y;
        VXt[lj][lc] = tvx.x; VXt[lj][lc+1] = tvx.y;
        VYt[lj][lc] = tvy.x; VYt[lj][lc+1] = tvy.y;
        float2 tw0 = *(const float2*)&fc1w[(2*(jc+lj)  )*KD + k0 + lc];
        float2 tw1 = *(const float2*)&fc1w[(2*(jc+lj)+1)*KD + k0 + lc];
        W0t[lj][lc] = tw0.x; W0t[lj][lc+1] = tw0.y;
        W1t[lj][lc] = tw1.x; W1t[lj][lc+1] = tw1.y;
        __syncthreads();
        #pragma unroll
        for (int kk = 0; kk < 16; kk++) {
            float v0 = Vt [kk][ty*2], v1 = Vt [kk][ty*2+1];
            float x0 = VXt[kk][ty*2], x1 = VXt[kk][ty*2+1];
            float y0 = VYt[kk][ty*2], y1 = VYt[kk][ty*2+1];
            float w00 = W0t[kk][tx*2], w01 = W0t[kk][tx*2+1];
            float w10 = W1t[kk][tx*2], w11 = W1t[kk][tx*2+1];
            s0[0][0] += v0*w00; s0[0][1] += v0*w01;
            s0[1][0] += v1*w00; s0[1][1] += v1*w01;
            s1[0][0] += v0*w10; s1[0][1] += v0*w11;
            s1[1][0] += v1*w10; s1[1][1] += v1*w11;
            su[0][0] += x0*w00 + y0*w10; su[0][1] += x0*w01 + y0*w11;
            su[1][0] += x1*w00 + y1*w10; su[1][1] += x1*w01 + y1*w11;
        }
        __syncthreads();
    }
    #pragma unroll
    for (int i = 0; i < 2; i++) {
        int bt = bt0 + ty*2 + i;
        #pragma unroll
        for (int jx = 0; jx < 2; jx++) {
            int k = k0 + tx*2 + jx;
            d_S[(0*BT + bt)*KD + k] = s0[i][jx];
            d_S[(1*BT + bt)*KD + k] = s1[i][jx];
            d_S[(2*BT + bt)*KD + k] = su[i][jx];
        }
    }
}

// ---------------------------------------------------------------------------
// cvec[o] = fc_out_b[o] + sum_k fc1_b[k] * W2_top[k,o]
// ---------------------------------------------------------------------------
__global__ void cvec_kernel(const float* __restrict__ fc1b,
                            const float* __restrict__ fcoutw,
                            const float* __restrict__ fcoutb) {
    int o = blockIdx.x * 256 + threadIdx.x;
    float acc = fcoutb[o];
    #pragma unroll 4
    for (int k = 0; k < KD; k++)
        acc += fc1b[k] * fcoutw[k*DOUT + o];
    d_cvec[o] = acc;
}

// ---------------------------------------------------------------------------
// stage2: unified GEMM, C (1024 x 768), K = 512.
//   rows    0..767 : A = d_S   (768x512), B = W2_top = fc_out_w[0:512]
//   rows 768..1023 : A = pos   (256x512), B = W2_bot = fc_out_w[512:1024], +cvec
// grid=(12 o-tiles of 64, 8 row-tiles of 128), block=256, microtile 8x4
// ---------------------------------------------------------------------------
__global__ void stage2_kernel(const float* __restrict__ fcoutw,
                              const float* __restrict__ pos) {
    __shared__ float At[16][128];
    __shared__ float Bt[16][64];
    int bx = blockIdx.x;           // o tile
    int by = blockIdx.y;           // row tile
    bool isBase = (by >= 6);
    const float* Ap = isBase ? (pos + (by-6)*128*KD)
                             : ((const float*)d_S + by*128*KD);
    const float* Bp = fcoutw + (isBase ? KD*DOUT : 0) + bx*64;
    int t  = threadIdx.x;
    int tx = t & 15;    // 4 cols
    int ty = t >> 4;    // 8 rows
    float acc[8][4];
    #pragma unroll
    for (int i = 0; i < 8; i++)
        #pragma unroll
        for (int j = 0; j < 4; j++) acc[i][j] = 0.f;

    int arow  = t >> 1;
    int akoff = (t & 1) * 8;
    int bkk   = t >> 4;
    int bo    = (t & 15) * 4;

    for (int kc = 0; kc < KD; kc += 16) {
        float4 a0 = *(const float4*)&Ap[arow*KD + kc + akoff];
        float4 a1 = *(const float4*)&Ap[arow*KD + kc + akoff + 4];
        At[akoff+0][arow] = a0.x; At[akoff+1][arow] = a0.y;
        At[akoff+2][arow] = a0.z; At[akoff+3][arow] = a0.w;
        At[akoff+4][arow] = a1.x; At[akoff+5][arow] = a1.y;
        At[akoff+6][arow] = a1.z; At[akoff+7][arow] = a1.w;
        *(float4*)&Bt[bkk][bo] = *(const float4*)&Bp[(kc+bkk)*DOUT + bo];
        __syncthreads();
        #pragma unroll
        for (int kk = 0; kk < 16; kk++) {
            float4 b4 = *(const float4*)&Bt[kk][tx*4];
            float4 aA = *(const float4*)&At[kk][ty*8];
            float4 aB = *(const float4*)&At[kk][ty*8 + 4];
            float av[8] = {aA.x,aA.y,aA.z,aA.w,aB.x,aB.y,aB.z,aB.w};
            float bv[4] = {b4.x,b4.y,b4.z,b4.w};
            #pragma unroll
            for (int i = 0; i < 8; i++)
                #pragma unroll
                for (int j = 0; j < 4; j++)
                    acc[i][j] += av[i]*bv[j];
        }
        __syncthreads();
    }
    int row0 = by*128 + ty*8;
    int col  = bx*64 + tx*4;
    float4 cadd = make_float4(0.f,0.f,0.f,0.f);
    if (isBase) {
        cadd.x = d_cvec[col];   cadd.y = d_cvec[col+1];
        cadd.z = d_cvec[col+2]; cadd.w = d_cvec[col+3];
    }
    #pragma unroll
    for (int i = 0; i < 8; i++) {
        float4 r;
        r.x = acc[i][0] + cadd.x; r.y = acc[i][1] + cadd.y;
        r.z = acc[i][2] + cadd.z; r.w = acc[i][3] + cadd.w;
        *(float4*)&d_AB[(row0+i)*DOUT + col] = r;
    }
}

// ---------------------------------------------------------------------------
// epilogue: out[bt,m,o] = VX*A0 + VY*A1 - V*AU + base[m,o]
// grid=(128 bt-pairs, 8 m-tiles of 32), block=192 (one float4 column each)
// ---------------------------------------------------------------------------
__global__ void epilogue_kernel(float* __restrict__ out) {
    __shared__ float4 A0s[2][192], A1s[2][192], AUs[2][192];
    int bt0 = blockIdx.x * 2;
    int m0  = blockIdx.y * 32;
    int t   = threadIdx.x;     // 0..191
    #pragma unroll
    for (int i = 0; i < 2; i++) {
        A0s[i][t] = ((const float4*)&d_AB[(0*BT + bt0+i)*DOUT])[t];
        A1s[i][t] = ((const float4*)&d_AB[(1*BT + bt0+i)*DOUT])[t];
        AUs[i][t] = ((const float4*)&d_AB[(2*BT + bt0+i)*DOUT])[t];
    }
    __syncthreads();
    #pragma unroll
    for (int i = 0; i < 2; i++) {
        int bt = bt0 + i;
        float4 a0 = A0s[i][t], a1 = A1s[i][t], au = AUs[i][t];
        #pragma unroll 4
        for (int mm = 0; mm < 32; mm++) {
            int m = m0 + mm;
            float v  = d_V [m*BT + bt];
            float vx = d_VX[m*BT + bt];
            float vy = d_VY[m*BT + bt];
            float4 base = ((const float4*)&d_AB[(3*BT + m)*DOUT])[t];
            float4 o4;
            o4.x = fmaf(vx, a0.x, fmaf(vy, a1.x, fmaf(-v, au.x, base.x)));
            o4.y = fmaf(vx, a0.y, fmaf(vy, a1.y, fmaf(-v, au.y, base.y)));
            o4.z = fmaf(vx, a0.z, fmaf(vy, a1.z, fmaf(-v, au.z, base.z)));
            o4.w = fmaf(vx, a0.w, fmaf(vy, a1.w, fmaf(-v, au.w, base.w)));
            ((float4*)out)[(bt*Mm + m)*(DOUT/4) + t] = o4;
        }
    }
}

// ---------------------------------------------------------------------------
extern "C" void kernel_launch(void* const* d_in, const int* in_sizes, int n_in,
                              void* d_out, int out_size) {
    const float* coords = (const float*)d_in[0];
    const float* vis    = (const float*)d_in[1];
    const float* pos    = (const float*)d_in[2];
    const float* fc1w   = (const float*)d_in[3];
    const float* fc1b   = (const float*)d_in[4];
    const float* fcoutw = (const float*)d_in[5];
    const float* fcoutb = (const float*)d_in[6];
    float* out = (float*)d_out;

    prep_kernel   <<<Mm, 256>>>(coords, vis);
    stage1_kernel <<<dim3(8,16), 256>>>(fc1w);
    cvec_kernel   <<<3, 256>>>(fc1b, fcoutw, fcoutb);
    stage2_kernel <<<dim3(12,8), 256>>>(fcoutw, pos);
    epilogue_kernel<<<dim3(128,8), 192>>>(out);
}

// round 2
// speedup vs baseline: 1.9657x; 1.9657x over previous
#include <cuda_runtime.h>
#include <cstdint>

#define Bb 4
#define Mm 256
#define Tt 64
#define BT 256      // B*T
#define KD 512      // 2M == D_MOT == D_ABS
#define DOUT 768
#define JSPLIT 4
#define KSPLIT 2

// Scratch (no allocation allowed -> __device__ globals)
__device__ float d_V [Mm*BT];              // V [j][bt]
__device__ float d_VX[Mm*BT];
__device__ float d_VY[Mm*BT];
__device__ float d_S1p[JSPLIT*3*BT*KD];    // stage1 partials
__device__ float d_S [3*BT*KD];            // S rows: [S0;S1;SU] (768 x 512)
__device__ float d_cvec[DOUT];             // fc1_b@W2_top + fc_out_b
__device__ float d_S2p[KSPLIT*1024*DOUT];  // stage2 partials
__device__ float d_AB[1024*DOUT];          // rows 0..767: A0/A1/AU ; 768..1023: base[m]

__device__ __forceinline__ bool is_nan_bits(float x) {
    return (__float_as_uint(x) & 0x7fffffffu) > 0x7f800000u;
}

// ---------------------------------------------------------------------------
// prep: build V/VX/VY in (j, bt) layout.  grid=(256 j), block=256 (bt)
// ---------------------------------------------------------------------------
__global__ void prep_kernel(const float* __restrict__ coords,
                            const float* __restrict__ vis) {
    int j = blockIdx.x;
    int t = threadIdx.x;           // bt = b*64 + tt
    int b = t >> 6, tt = t & 63;
    int idx = (b*Mm + j)*Tt + tt;
    float2 xy = ((const float2*)coords)[idx];
    float v = vis[idx];
    float x = xy.x, y = xy.y;
    if (is_nan_bits(x)) { v = 0.f; x = 0.f; }
    if (is_nan_bits(y)) { y = 0.f; }
    int o = j*BT + t;
    d_V [o] = v;
    d_VX[o] = x * v;
    d_VY[o] = y * v;
}

// ---------------------------------------------------------------------------
// stage1: S0 = V@We, S1 = V@Wo, SU = VX@We + VY@Wo   (contraction over j)
// grid=(4 bt-tiles x64, 8 k-tiles x64, JSPLIT j-splits x64), block=256
// microtile 4bt x 4k, float4 LDS (5 LDS.128 per 64 FMA)
// ---------------------------------------------------------------------------
__global__ void stage1_kernel(const float* __restrict__ fc1w) {
    __shared__ float Vt [16][64], VXt[16][64], VYt[16][64];
    __shared__ float W0t[16][64], W1t[16][64];
    int bt0 = blockIdx.x * 64;
    int k0  = blockIdx.y * 64;
    int js  = blockIdx.z;
    int jb  = js * 64;
    int t  = threadIdx.x;
    int tx = t & 15;       // k quad
    int ty = t >> 4;       // bt quad
    float s0[4][4], s1[4][4], su[4][4];
    #pragma unroll
    for (int i = 0; i < 4; i++)
        #pragma unroll
        for (int j = 0; j < 4; j++) { s0[i][j]=0.f; s1[i][j]=0.f; su[i][j]=0.f; }

    int lj = t >> 4;           // load row 0..15
    int lc = (t & 15) * 4;     // load col quad

    for (int jc = 0; jc < 64; jc += 16) {
        int jrow = jb + jc + lj;
        *(float4*)&Vt [lj][lc] = *(const float4*)&d_V [jrow*BT + bt0 + lc];
        *(float4*)&VXt[lj][lc] = *(const float4*)&d_VX[jrow*BT + bt0 + lc];
        *(float4*)&VYt[lj][lc] = *(const float4*)&d_VY[jrow*BT + bt0 + lc];
        *(float4*)&W0t[lj][lc] = *(const float4*)&fc1w[(2*jrow  )*KD + k0 + lc];
        *(float4*)&W1t[lj][lc] = *(const float4*)&fc1w[(2*jrow+1)*KD + k0 + lc];
        __syncthreads();
        #pragma unroll
        for (int kk = 0; kk < 16; kk++) {
            float4 v4 = *(const float4*)&Vt [kk][ty*4];
            float4 x4 = *(const float4*)&VXt[kk][ty*4];
            float4 y4 = *(const float4*)&VYt[kk][ty*4];
            float4 w0 = *(const float4*)&W0t[kk][tx*4];
            float4 w1 = *(const float4*)&W1t[kk][tx*4];
            float vv[4] = {v4.x,v4.y,v4.z,v4.w};
            float xx[4] = {x4.x,x4.y,x4.z,x4.w};
            float yy[4] = {y4.x,y4.y,y4.z,y4.w};
            float a0[4] = {w0.x,w0.y,w0.z,w0.w};
            float a1[4] = {w1.x,w1.y,w1.z,w1.w};
            #pragma unroll
            for (int i = 0; i < 4; i++)
                #pragma unroll
                for (int j = 0; j < 4; j++) {
                    s0[i][j] = fmaf(vv[i], a0[j], s0[i][j]);
                    s1[i][j] = fmaf(vv[i], a1[j], s1[i][j]);
                    su[i][j] = fmaf(xx[i], a0[j], fmaf(yy[i], a1[j], su[i][j]));
                }
        }
        __syncthreads();
    }
    float* base = d_S1p + (size_t)js*3*BT*KD;
    #pragma unroll
    for (int i = 0; i < 4; i++) {
        int bt = bt0 + ty*4 + i;
        int k  = k0 + tx*4;
        *(float4*)&base[(0*BT + bt)*KD + k] = make_float4(s0[i][0],s0[i][1],s0[i][2],s0[i][3]);
        *(float4*)&base[(1*BT + bt)*KD + k] = make_float4(s1[i][0],s1[i][1],s1[i][2],s1[i][3]);
        *(float4*)&base[(2*BT + bt)*KD + k] = make_float4(su[i][0],su[i][1],su[i][2],su[i][3]);
    }
}

// combine stage1 partials: d_S = sum over JSPLIT planes
__global__ void combine1_kernel() {
    int idx = blockIdx.x * 256 + threadIdx.x;   // float4 index, 98304 total
    const float4* p = (const float4*)d_S1p;
    const int plane = 3*BT*KD/4;
    float4 a = p[idx], b = p[plane + idx], c = p[2*plane + idx], d = p[3*plane + idx];
    float4 r;
    r.x = (a.x+b.x)+(c.x+d.x); r.y = (a.y+b.y)+(c.y+d.y);
    r.z = (a.z+b.z)+(c.z+d.z); r.w = (a.w+b.w)+(c.w+d.w);
    ((float4*)d_S)[idx] = r;
}

// ---------------------------------------------------------------------------
// cvec[o] = fc_out_b[o] + sum_k fc1_b[k] * W2_top[k,o]
// grid=12 blocks x 64 o each; 4-way k split per o + smem reduce
// ---------------------------------------------------------------------------
__global__ void cvec_kernel(const float* __restrict__ fc1b,
                            const float* __restrict__ fcoutw,
                            const float* __restrict__ fcoutb) {
    __shared__ float sb[KD];
    __shared__ float red[256];
    int t = threadIdx.x;
    sb[t] = fc1b[t];
    sb[t+256] = fc1b[t+256];
    __syncthreads();
    int o  = blockIdx.x * 64 + (t & 63);
    int kg = t >> 6;                     // 0..3, 128 k each
    float acc = 0.f;
    int k0 = kg * 128;
    #pragma unroll 8
    for (int k = 0; k < 128; k++)
        acc = fmaf(sb[k0 + k], fcoutw[(k0 + k)*DOUT + o], acc);
    red[t] = acc;
    __syncthreads();
    if (kg == 0) {
        float total = red[t] + red[t+64] + red[t+128] + red[t+192] + fcoutb[o];
        d_cvec[o] = total;
    }
}

// ---------------------------------------------------------------------------
// stage2: C (1024 x 768) = A (1024 x 512) @ B (512 x 768), split-K=2
//   rows    0..767 : A = d_S, B = W2_top
//   rows 768..1023 : A = pos, B = W2_bot
// grid=(12 n x64, 16 m x64, 2 ksplit), block=128, microtile 8x4
// ---------------------------------------------------------------------------
__global__ void stage2_kernel(const float* __restrict__ fcoutw,
                              const float* __restrict__ pos) {
    __shared__ float At[16][64];
    __shared__ float Bt[16][64];
    int bx = blockIdx.x;           // n tile
    int by = blockIdx.y;           // m tile
    int bz = blockIdx.z;           // k split
    bool isBase = (by >= 12);
    const float* Ap = isBase ? (pos + (by-12)*64*KD)
                             : ((const float*)d_S + by*64*KD);
    const float* Bp = fcoutw + (isBase ? KD*DOUT : 0) + bx*64;
    int t  = threadIdx.x;
    int tx = t & 15;    // 4 cols
    int ty = t >> 4;    // 8 rows
    float acc[8][4];
    #pragma unroll
    for (int i = 0; i < 8; i++)
        #pragma unroll
        for (int j = 0; j < 4; j++) acc[i][j] = 0.f;

    int arow = t >> 1;          // 0..63
    int koff = (t & 1) * 8;
    int bk   = t >> 4;          // 0..7 (and +8)
    int bn   = (t & 15) * 4;

    int kend = bz*256 + 256;
    for (int kc = bz*256; kc < kend; kc += 16) {
        float4 a0 = *(const float4*)&Ap[arow*KD + kc + koff];
        float4 a1 = *(const float4*)&Ap[arow*KD + kc + koff + 4];
        At[koff+0][arow] = a0.x; At[koff+1][arow] = a0.y;
        At[koff+2][arow] = a0.z; At[koff+3][arow] = a0.w;
        At[koff+4][arow] = a1.x; At[koff+5][arow] = a1.y;
        At[koff+6][arow] = a1.z; At[koff+7][arow] = a1.w;
        *(float4*)&Bt[bk  ][bn] = *(const float4*)&Bp[(kc+bk  )*DOUT + bn];
        *(float4*)&Bt[bk+8][bn] = *(const float4*)&Bp[(kc+bk+8)*DOUT + bn];
        __syncthreads();
        #pragma unroll
        for (int kk = 0; kk < 16; kk++) {
            float4 b4 = *(const float4*)&Bt[kk][tx*4];
            float4 aA = *(const float4*)&At[kk][ty*8];
            float4 aB = *(const float4*)&At[kk][ty*8 + 4];
            float av[8] = {aA.x,aA.y,aA.z,aA.w,aB.x,aB.y,aB.z,aB.w};
            float bv[4] = {b4.x,b4.y,b4.z,b4.w};
            #pragma unroll
            for (int i = 0; i < 8; i++)
                #pragma unroll
                for (int j = 0; j < 4; j++)
                    acc[i][j] = fmaf(av[i], bv[j], acc[i][j]);
        }
        __syncthreads();
    }
    float* outp = d_S2p + (size_t)bz*1024*DOUT;
    int row0 = by*64 + ty*8;
    int col  = bx*64 + tx*4;
    #pragma unroll
    for (int i = 0; i < 8; i++)
        *(float4*)&outp[(row0+i)*DOUT + col] =
            make_float4(acc[i][0],acc[i][1],acc[i][2],acc[i][3]);
}

// combine stage2 partials + add cvec to base rows
__global__ void combine2_kernel() {
    int idx = blockIdx.x * 256 + threadIdx.x;    // float4 index, 196608 total
    const float4* p = (const float4*)d_S2p;
    const int plane = 1024*DOUT/4;
    float4 a = p[idx], b = p[plane + idx];
    float4 r = make_float4(a.x+b.x, a.y+b.y, a.z+b.z, a.w+b.w);
    int row = idx / (DOUT/4);
    if (row >= 768) {
        float4 cv = ((const float4*)d_cvec)[idx % (DOUT/4)];
        r.x += cv.x; r.y += cv.y; r.z += cv.z; r.w += cv.w;
    }
    ((float4*)d_AB)[idx] = r;
}

// ---------------------------------------------------------------------------
// epilogue: out[bt,m,o] = VX*A0 + VY*A1 - V*AU + base[m,o]
// grid=(64 bt-quads, 8 m-tiles x32), block=192 (one float4 column each)
// ---------------------------------------------------------------------------
__global__ void epilogue_kernel(float* __restrict__ out) {
    __shared__ float4 A0s[4][192], A1s[4][192], AUs[4][192];
    __shared__ float sV[32][4], sVX[32][4], sVY[32][4];
    int bt0 = blockIdx.x * 4;
    int m0  = blockIdx.y * 32;
    int t   = threadIdx.x;     // 0..191
    #pragma unroll
    for (int i = 0; i < 4; i++) {
        A0s[i][t] = ((const float4*)&d_AB[(0*BT + bt0+i)*DOUT])[t];
        A1s[i][t] = ((const float4*)&d_AB[(1*BT + bt0+i)*DOUT])[t];
        AUs[i][t] = ((const float4*)&d_AB[(2*BT + bt0+i)*DOUT])[t];
    }
    if (t < 128) {
        int mm = t >> 2, bi = t & 3;
        int src = (m0+mm)*BT + bt0 + bi;
        sV [mm][bi] = d_V [src];
        sVX[mm][bi] = d_VX[src];
        sVY[mm][bi] = d_VY[src];
    }
    __syncthreads();

    float4 a0[4], a1[4], au[4];
    #pragma unroll
    for (int i = 0; i < 4; i++) { a0[i]=A0s[i][t]; a1[i]=A1s[i][t]; au[i]=AUs[i][t]; }

    #pragma unroll 2
    for (int mm = 0; mm < 32; mm++) {
        int m = m0 + mm;
        float4 base = ((const float4*)&d_AB[(768 + m)*DOUT])[t];
        float4 v4  = *(const float4*)&sV [mm][0];
        float4 vx4 = *(const float4*)&sVX[mm][0];
        float4 vy4 = *(const float4*)&sVY[mm][0];
        float vv[4] = {v4.x,v4.y,v4.z,v4.w};
        float xx[4] = {vx4.x,vx4.y,vx4.z,vx4.w};
        float yy[4] = {vy4.x,vy4.y,vy4.z,vy4.w};
        #pragma unroll
        for (int i = 0; i < 4; i++) {
            float4 o4;
            o4.x = fmaf(xx[i], a0[i].x, fmaf(yy[i], a1[i].x, fmaf(-vv[i], au[i].x, base.x)));
            o4.y = fmaf(xx[i], a0[i].y, fmaf(yy[i], a1[i].y, fmaf(-vv[i], au[i].y, base.y)));
            o4.z = fmaf(xx[i], a0[i].z, fmaf(yy[i], a1[i].z, fmaf(-vv[i], au[i].z, base.z)));
            o4.w = fmaf(xx[i], a0[i].w, fmaf(yy[i], a1[i].w, fmaf(-vv[i], au[i].w, base.w)));
            ((float4*)out)[((bt0+i)*Mm + m)*(DOUT/4) + t] = o4;
        }
    }
}

// ---------------------------------------------------------------------------
extern "C" void kernel_launch(void* const* d_in, const int* in_sizes, int n_in,
                              void* d_out, int out_size) {
    const float* coords = (const float*)d_in[0];
    const float* vis    = (const float*)d_in[1];
    const float* pos    = (const float*)d_in[2];
    const float* fc1w   = (const float*)d_in[3];
    const float* fc1b   = (const float*)d_in[4];
    const float* fcoutw = (const float*)d_in[5];
    const float* fcoutb = (const float*)d_in[6];
    float* out = (float*)d_out;

    prep_kernel    <<<Mm, 256>>>(coords, vis);
    stage1_kernel  <<<dim3(4,8,JSPLIT), 256>>>(fc1w);
    combine1_kernel<<<384, 256>>>();
    cvec_kernel    <<<12, 256>>>(fc1b, fcoutw, fcoutb);
    stage2_kernel  <<<dim3(12,16,KSPLIT), 128>>>(fcoutw, pos);
    combine2_kernel<<<768, 256>>>();
    epilogue_kernel<<<dim3(64,8), 192>>>(out);
}

// round 3
// speedup vs baseline: 2.3065x; 1.1734x over previous
#include <cuda_runtime.h>
#include <cstdint>

#define Bb 4
#define Mm 256
#define Tt 64
#define BT 256      // B*T
#define KD 512      // 2M == D_MOT == D_ABS
#define DOUT 768
#define JSPLIT 4
#define KSPLIT 2
#define CSPLIT 4

// Scratch (no allocation allowed -> __device__ globals)
__device__ float d_V [Mm*BT];              // V [j][bt]
__device__ float d_VX[Mm*BT];
__device__ float d_VY[Mm*BT];
__device__ float d_S1p[JSPLIT*3*BT*KD];    // stage1 partials
__device__ float d_S [3*BT*KD];            // S rows: [S0;S1;SU] (768 x 512)
__device__ float d_cvp[CSPLIT*DOUT];       // cvec partials (plane0 includes fcoutb)
__device__ float d_S2p[KSPLIT*1024*DOUT];  // stage2 partials (rows 0..767 A, 768..1023 base)

__device__ __forceinline__ bool is_nan_bits(float x) {
    return (__float_as_uint(x) & 0x7fffffffu) > 0x7f800000u;
}

// ---------------------------------------------------------------------------
// prep: build V/VX/VY in (j, bt) layout.  grid=(256 j), block=256 (bt)
// ---------------------------------------------------------------------------
__global__ void prep_kernel(const float* __restrict__ coords,
                            const float* __restrict__ vis) {
    int j = blockIdx.x;
    int t = threadIdx.x;           // bt = b*64 + tt
    int b = t >> 6, tt = t & 63;
    int idx = (b*Mm + j)*Tt + tt;
    float2 xy = ((const float2*)coords)[idx];
    float v = vis[idx];
    float x = xy.x, y = xy.y;
    if (is_nan_bits(x)) { v = 0.f; x = 0.f; }
    if (is_nan_bits(y)) { y = 0.f; }
    int o = j*BT + t;
    d_V [o] = v;
    d_VX[o] = x * v;
    d_VY[o] = y * v;
}

// ---------------------------------------------------------------------------
// stage1: S0 = V@We, S1 = V@Wo, SU = VX@We + VY@Wo   (contraction over j)
// grid=(4 bt-tiles x64, 8 k-tiles x64, JSPLIT j-splits x64), block=256
// ---------------------------------------------------------------------------
__global__ void stage1_kernel(const float* __restrict__ fc1w) {
    __shared__ float Vt [16][64], VXt[16][64], VYt[16][64];
    __shared__ float W0t[16][64], W1t[16][64];
    int bt0 = blockIdx.x * 64;
    int k0  = blockIdx.y * 64;
    int js  = blockIdx.z;
    int jb  = js * 64;
    int t  = threadIdx.x;
    int tx = t & 15;       // k quad
    int ty = t >> 4;       // bt quad
    float s0[4][4], s1[4][4], su[4][4];
    #pragma unroll
    for (int i = 0; i < 4; i++)
        #pragma unroll
        for (int j = 0; j < 4; j++) { s0[i][j]=0.f; s1[i][j]=0.f; su[i][j]=0.f; }

    int lj = t >> 4;           // load row 0..15
    int lc = (t & 15) * 4;     // load col quad

    for (int jc = 0; jc < 64; jc += 16) {
        int jrow = jb + jc + lj;
        *(float4*)&Vt [lj][lc] = *(const float4*)&d_V [jrow*BT + bt0 + lc];
        *(float4*)&VXt[lj][lc] = *(const float4*)&d_VX[jrow*BT + bt0 + lc];
        *(float4*)&VYt[lj][lc] = *(const float4*)&d_VY[jrow*BT + bt0 + lc];
        *(float4*)&W0t[lj][lc] = *(const float4*)&fc1w[(2*jrow  )*KD + k0 + lc];
        *(float4*)&W1t[lj][lc] = *(const float4*)&fc1w[(2*jrow+1)*KD + k0 + lc];
        __syncthreads();
        #pragma unroll
        for (int kk = 0; kk < 16; kk++) {
            float4 v4 = *(const float4*)&Vt [kk][ty*4];
            float4 x4 = *(const float4*)&VXt[kk][ty*4];
            float4 y4 = *(const float4*)&VYt[kk][ty*4];
            float4 w0 = *(const float4*)&W0t[kk][tx*4];
            float4 w1 = *(const float4*)&W1t[kk][tx*4];
            float vv[4] = {v4.x,v4.y,v4.z,v4.w};
            float xx[4] = {x4.x,x4.y,x4.z,x4.w};
            float yy[4] = {y4.x,y4.y,y4.z,y4.w};
            float a0[4] = {w0.x,w0.y,w0.z,w0.w};
            float a1[4] = {w1.x,w1.y,w1.z,w1.w};
            #pragma unroll
            for (int i = 0; i < 4; i++)
                #pragma unroll
                for (int j = 0; j < 4; j++) {
                    s0[i][j] = fmaf(vv[i], a0[j], s0[i][j]);
                    s1[i][j] = fmaf(vv[i], a1[j], s1[i][j]);
                    su[i][j] = fmaf(xx[i], a0[j], fmaf(yy[i], a1[j], su[i][j]));
                }
        }
        __syncthreads();
    }
    float* base = d_S1p + (size_t)js*3*BT*KD;
    #pragma unroll
    for (int i = 0; i < 4; i++) {
        int bt = bt0 + ty*4 + i;
        int k  = k0 + tx*4;
        *(float4*)&base[(0*BT + bt)*KD + k] = make_float4(s0[i][0],s0[i][1],s0[i][2],s0[i][3]);
        *(float4*)&base[(1*BT + bt)*KD + k] = make_float4(s1[i][0],s1[i][1],s1[i][2],s1[i][3]);
        *(float4*)&base[(2*BT + bt)*KD + k] = make_float4(su[i][0],su[i][1],su[i][2],su[i][3]);
    }
}

// combine stage1 partials: d_S = sum over JSPLIT planes
__global__ void combine1_kernel() {
    int idx = blockIdx.x * 256 + threadIdx.x;   // float4 index, 98304 total
    const float4* p = (const float4*)d_S1p;
    const int plane = 3*BT*KD/4;
    float4 a = p[idx], b = p[plane + idx], c = p[2*plane + idx], d = p[3*plane + idx];
    float4 r;
    r.x = (a.x+b.x)+(c.x+d.x); r.y = (a.y+b.y)+(c.y+d.y);
    r.z = (a.z+b.z)+(c.z+d.z); r.w = (a.w+b.w)+(c.w+d.w);
    ((float4*)d_S)[idx] = r;
}

// ---------------------------------------------------------------------------
// cvec partials: d_cvp[bz][o] = sum_{k in bz-slice} fc1_b[k]*W2_top[k,o]
//                (+ fc_out_b[o] folded into plane 0)
// grid=(12, CSPLIT), block=256: 64 o x 4 kg x 32 k
// ---------------------------------------------------------------------------
__global__ void cvec_kernel(const float* __restrict__ fc1b,
                            const float* __restrict__ fcoutw,
                            const float* __restrict__ fcoutb) {
    __shared__ float red[256];
    int t  = threadIdx.x;
    int o  = blockIdx.x * 64 + (t & 63);
    int bz = blockIdx.y;
    int kg = t >> 6;
    int k0 = bz * (KD/CSPLIT) + kg * 32;
    float acc = 0.f;
    #pragma unroll 8
    for (int k = 0; k < 32; k++)
        acc = fmaf(fc1b[k0 + k], fcoutw[(k0 + k)*DOUT + o], acc);
    red[t] = acc;
    __syncthreads();
    if (kg == 0) {
        float total = red[t] + red[t+64] + red[t+128] + red[t+192];
        if (bz == 0) total += fcoutb[o];
        d_cvp[bz*DOUT + o] = total;
    }
}

// ---------------------------------------------------------------------------
// stage2: C (1024 x 768) = A (1024 x 512) @ B (512 x 768), split-K=2
//   rows    0..767 : A = d_S, B = W2_top
//   rows 768..1023 : A = pos, B = W2_bot
// grid=(12 n x64, 16 m x64, 2 ksplit), block=128, microtile 8x4
// ---------------------------------------------------------------------------
__global__ void stage2_kernel(const float* __restrict__ fcoutw,
                              const float* __restrict__ pos) {
    __shared__ float At[16][64];
    __shared__ float Bt[16][64];
    int bx = blockIdx.x;           // n tile
    int by = blockIdx.y;           // m tile
    int bz = blockIdx.z;           // k split
    bool isBase = (by >= 12);
    const float* Ap = isBase ? (pos + (by-12)*64*KD)
                             : ((const float*)d_S + by*64*KD);
    const float* Bp = fcoutw + (isBase ? KD*DOUT : 0) + bx*64;
    int t  = threadIdx.x;
    int tx = t & 15;    // 4 cols
    int ty = t >> 4;    // 8 rows
    float acc[8][4];
    #pragma unroll
    for (int i = 0; i < 8; i++)
        #pragma unroll
        for (int j = 0; j < 4; j++) acc[i][j] = 0.f;

    int arow = t >> 1;          // 0..63
    int koff = (t & 1) * 8;
    int bk   = t >> 4;          // 0..7 (and +8)
    int bn   = (t & 15) * 4;

    int kend = bz*256 + 256;
    for (int kc = bz*256; kc < kend; kc += 16) {
        float4 a0 = *(const float4*)&Ap[arow*KD + kc + koff];
        float4 a1 = *(const float4*)&Ap[arow*KD + kc + koff + 4];
        At[koff+0][arow] = a0.x; At[koff+1][arow] = a0.y;
        At[koff+2][arow] = a0.z; At[koff+3][arow] = a0.w;
        At[koff+4][arow] = a1.x; At[koff+5][arow] = a1.y;
        At[koff+6][arow] = a1.z; At[koff+7][arow] = a1.w;
        *(float4*)&Bt[bk  ][bn] = *(const float4*)&Bp[(kc+bk  )*DOUT + bn];
        *(float4*)&Bt[bk+8][bn] = *(const float4*)&Bp[(kc+bk+8)*DOUT + bn];
        __syncthreads();
        #pragma unroll
        for (int kk = 0; kk < 16; kk++) {
            float4 b4 = *(const float4*)&Bt[kk][tx*4];
            float4 aA = *(const float4*)&At[kk][ty*8];
            float4 aB = *(const float4*)&At[kk][ty*8 + 4];
            float av[8] = {aA.x,aA.y,aA.z,aA.w,aB.x,aB.y,aB.z,aB.w};
            float bv[4] = {b4.x,b4.y,b4.z,b4.w};
            #pragma unroll
            for (int i = 0; i < 8; i++)
                #pragma unroll
                for (int j = 0; j < 4; j++)
                    acc[i][j] = fmaf(av[i], bv[j], acc[i][j]);
        }
        __syncthreads();
    }
    float* outp = d_S2p + (size_t)bz*1024*DOUT;
    int row0 = by*64 + ty*8;
    int col  = bx*64 + tx*4;
    #pragma unroll
    for (int i = 0; i < 8; i++)
        *(float4*)&outp[(row0+i)*DOUT + col] =
            make_float4(acc[i][0],acc[i][1],acc[i][2],acc[i][3]);
}

// ---------------------------------------------------------------------------
// epilogue (fused combine2 + cvec + base):
//   out[bt,m,o] = VX*A0 + VY*A1 - V*AU + pos@W2_bot + cvec
// where A* and the pos term are sums of the KSPLIT stage2 planes.
// grid=(32 bt-octets, 8 m-tiles x32), block=192 (one float4 column each)
// dynamic smem: A rows for 8 bt (3*8*192 float4 = 72 KB) + V/VX/VY scalars
// ---------------------------------------------------------------------------
#define EPI_BT 8
__global__ void epilogue_kernel(float* __restrict__ out) {
    extern __shared__ float4 sm[];
    float4* A0s = sm;                       // [EPI_BT][192]
    float4* A1s = sm + EPI_BT*192;
    float4* AUs = sm + 2*EPI_BT*192;
    float*  sV  = (float*)(sm + 3*EPI_BT*192);        // [32][EPI_BT]
    float*  sVX = sV  + 32*EPI_BT;
    float*  sVY = sVX + 32*EPI_BT;

    int bt0 = blockIdx.x * EPI_BT;
    int m0  = blockIdx.y * 32;
    int t   = threadIdx.x;     // 0..191

    const float4* p0 = (const float4*)d_S2p;
    const float4* p1 = (const float4*)(d_S2p + (size_t)1024*DOUT);

    #pragma unroll
    for (int i = 0; i < EPI_BT; i++) {
        int r0 = (0*BT + bt0+i)*(DOUT/4) + t;
        int r1 = (1*BT + bt0+i)*(DOUT/4) + t;
        int r2 = (2*BT + bt0+i)*(DOUT/4) + t;
        float4 a = p0[r0], b = p1[r0];
        A0s[i*192+t] = make_float4(a.x+b.x, a.y+b.y, a.z+b.z, a.w+b.w);
        a = p0[r1]; b = p1[r1];
        A1s[i*192+t] = make_float4(a.x+b.x, a.y+b.y, a.z+b.z, a.w+b.w);
        a = p0[r2]; b = p1[r2];
        AUs[i*192+t] = make_float4(a.x+b.x, a.y+b.y, a.z+b.z, a.w+b.w);
    }
    for (int idx = t; idx < 32*EPI_BT; idx += 192) {
        int mm = idx >> 3, bi = idx & 7;
        int src = (m0+mm)*BT + bt0 + bi;
        sV [idx] = d_V [src];
        sVX[idx] = d_VX[src];
        sVY[idx] = d_VY[src];
    }
    // cvec column (sum of CSPLIT partial planes)
    float4 cv;
    {
        const float4* cp = (const float4*)d_cvp;
        float4 c0 = cp[0*(DOUT/4)+t], c1 = cp[1*(DOUT/4)+t];
        float4 c2 = cp[2*(DOUT/4)+t], c3 = cp[3*(DOUT/4)+t];
        cv = make_float4((c0.x+c1.x)+(c2.x+c3.x), (c0.y+c1.y)+(c2.y+c3.y),
                         (c0.z+c1.z)+(c2.z+c3.z), (c0.w+c1.w)+(c2.w+c3.w));
    }
    __syncthreads();

    #pragma unroll 2
    for (int mm = 0; mm < 32; mm++) {
        int m = m0 + mm;
        int br = (768 + m)*(DOUT/4) + t;
        float4 b0 = p0[br], b1 = p1[br];
        float4 base = make_float4(b0.x+b1.x+cv.x, b0.y+b1.y+cv.y,
                                  b0.z+b1.z+cv.z, b0.w+b1.w+cv.w);
        #pragma unroll
        for (int i = 0; i < EPI_BT; i++) {
            float v  = sV [mm*EPI_BT+i];
            float vx = sVX[mm*EPI_BT+i];
            float vy = sVY[mm*EPI_BT+i];
            float4 a0 = A0s[i*192+t], a1 = A1s[i*192+t], au = AUs[i*192+t];
            float4 o4;
            o4.x = fmaf(vx, a0.x, fmaf(vy, a1.x, fmaf(-v, au.x, base.x)));
            o4.y = fmaf(vx, a0.y, fmaf(vy, a1.y, fmaf(-v, au.y, base.y)));
            o4.z = fmaf(vx, a0.z, fmaf(vy, a1.z, fmaf(-v, au.z, base.z)));
            o4.w = fmaf(vx, a0.w, fmaf(vy, a1.w, fmaf(-v, au.w, base.w)));
            ((float4*)out)[((bt0+i)*Mm + m)*(DOUT/4) + t] = o4;
        }
    }
}

// ---------------------------------------------------------------------------
extern "C" void kernel_launch(void* const* d_in, const int* in_sizes, int n_in,
                              void* d_out, int out_size) {
    const float* coords = (const float*)d_in[0];
    const float* vis    = (const float*)d_in[1];
    const float* pos    = (const float*)d_in[2];
    const float* fc1w   = (const float*)d_in[3];
    const float* fc1b   = (const float*)d_in[4];
    const float* fcoutw = (const float*)d_in[5];
    const float* fcoutb = (const float*)d_in[6];
    float* out = (float*)d_out;

    static int smem_set = 0;
    int epi_smem = 3*EPI_BT*192*16 + 3*32*EPI_BT*4;   // 76,416 B
    if (!smem_set) {
        cudaFuncSetAttribute(epilogue_kernel,
                             cudaFuncAttributeMaxDynamicSharedMemorySize, epi_smem);
        smem_set = 1;
    }

    prep_kernel    <<<Mm, 256>>>(coords, vis);
    stage1_kernel  <<<dim3(4,8,JSPLIT), 256>>>(fc1w);
    combine1_kernel<<<384, 256>>>();
    cvec_kernel    <<<dim3(12,CSPLIT), 256>>>(fc1b, fcoutw, fcoutb);
    stage2_kernel  <<<dim3(12,16,KSPLIT), 128>>>(fcoutw, pos);
    epilogue_kernel<<<dim3(BT/EPI_BT,8), 192, epi_smem>>>(out);
}